// round 16
// baseline (speedup 1.0000x reference)
#include <cuda_runtime.h>
#include <cuda_fp16.h>
#include <cstdint>
#include <cstddef>

#define BB 8192
#define DD 4096
#define HH 8192
#define TM 128
#define TN 256
#define CHUNKS 64             // 64 k-chunks of 64
#define NT 32
#define MT 64
#define A_BYTES 16384         // 128 rows * 128B
#define B_BYTES 32768         // 256 rows * 128B
#define STAGE_BYTES (A_BYTES + B_BYTES)
#define SMEM_DYN (1024 + 8192 + 4 * STAGE_BYTES)   // 205824
#define LN4F 1.3862944f
#define GUARD 2e-3f
#define MAXFIX 128

// ---------------- device scratch ----------------
__device__ uint4 g_x4[(size_t)BB * DD / 8];             // x as fp16
__device__ uint4 g_w4[2][(size_t)HH * DD / 8];          // [expert] w1^T fp16
__device__ float g_part[(size_t)2 * NT * BB * 2];
__device__ int   g_nfix;
__device__ int   g_fixrows[MAXFIX];
__device__ float g_fixpart[2 * MAXFIX * 32 * 2];

// ---------------- helpers ----------------
__device__ __forceinline__ uint32_t smem_u32(const void* p) {
    uint32_t a;
    asm("{ .reg .u64 t; cvta.to.shared.u64 t, %1; cvt.u32.u64 %0, t; }" : "=r"(a) : "l"(p));
    return a;
}
#define CPA16(sa, g) asm volatile("cp.async.cg.shared.global [%0], [%1], 16;" :: "r"(sa), "l"(g) : "memory")
// .noinc: arrive against the PRE-INITIALIZED expected count.
#define CPA_ARRIVE(a) asm volatile("cp.async.mbarrier.arrive.noinc.shared.b64 [%0];" :: "r"((uint32_t)(a)) : "memory")
#define MBAR_INIT(a, c) asm volatile("mbarrier.init.shared.b64 [%0], %1;" :: "r"((uint32_t)(a)), "r"((uint32_t)(c)) : "memory")
#define MBAR_ARRIVE(a) asm volatile("mbarrier.arrive.shared.b64 _, [%0];" :: "r"((uint32_t)(a)) : "memory")
#define MBAR_WAIT(a, ph) do { \
    uint32_t _m = (uint32_t)(a), _p = (uint32_t)(ph), _d; \
    asm volatile("{.reg .pred p; mbarrier.try_wait.parity.acquire.cta.shared::cta.b64 p, [%1], %2; selp.b32 %0,1,0,p;}" \
        : "=r"(_d) : "r"(_m), "r"(_p) : "memory"); \
    if (!_d) asm volatile("{.reg .pred P1; WL_%=: mbarrier.try_wait.parity.acquire.cta.shared::cta.b64 P1, [%0], %1, 0x989680; @P1 bra.uni WD_%=; bra.uni WL_%=; WD_%=:}" \
        :: "r"(_m), "r"(_p) : "memory"); \
} while (0)
// Lane-0-elected wait: one poller per warp, result broadcast by warp convergence.
#define MBAR_WAIT_W(a, ph, lane) do { \
    if ((lane) == 0) MBAR_WAIT(a, ph); \
    __syncwarp(); \
} while (0)

__device__ __forceinline__ void ldsm4(uint32_t* r, uint32_t addr) {
    asm volatile("ldmatrix.sync.aligned.m8n8.x4.shared.b16 {%0,%1,%2,%3}, [%4];"
                 : "=r"(r[0]), "=r"(r[1]), "=r"(r[2]), "=r"(r[3]) : "r"(addr));
}
__device__ __forceinline__ void mma16816(float* d, const uint32_t* a, const uint32_t* b) {
    asm volatile("mma.sync.aligned.m16n8k16.row.col.f32.f16.f16.f32 "
                 "{%0,%1,%2,%3}, {%4,%5,%6,%7}, {%8,%9}, {%0,%1,%2,%3};"
                 : "+f"(d[0]), "+f"(d[1]), "+f"(d[2]), "+f"(d[3])
                 : "r"(a[0]), "r"(a[1]), "r"(a[2]), "r"(a[3]), "r"(b[0]), "r"(b[1]));
}

// ---------------- kernel 1: x -> fp16 ----------------
__global__ void cvt_x_kernel(const float* __restrict__ x) {
    if (blockIdx.x == 0 && threadIdx.x == 0) g_nfix = 0;
    size_t i = (size_t)blockIdx.x * blockDim.x + threadIdx.x;
    if (i >= (size_t)BB * DD / 4) return;
    float4 v = reinterpret_cast<const float4*>(x)[i];
    __half2* px = reinterpret_cast<__half2*>(g_x4);
    px[2 * i]     = __floats2half2_rn(v.x, v.y);
    px[2 * i + 1] = __floats2half2_rn(v.z, v.w);
}

// ---------------- kernel 2: w1 [D,H] f32 -> W [H,D] fp16 (transpose) ----------
__global__ void cvt_w_kernel(const float* __restrict__ wt, const float* __restrict__ wf) {
    __shared__ float tile[32][33];
    const float* w = blockIdx.z ? wf : wt;
    __half* Wh = reinterpret_cast<__half*>(g_w4[blockIdx.z]);
    int h0 = blockIdx.x * 32, d0 = blockIdx.y * 32;
    int tx = threadIdx.x, ty = threadIdx.y;   // (32, 8)
#pragma unroll
    for (int i = 0; i < 4; i++)
        tile[ty + i * 8][tx] = w[(size_t)(d0 + ty + i * 8) * HH + h0 + tx];
    __syncthreads();
#pragma unroll
    for (int i = 0; i < 4; i++) {
        float v = tile[tx][ty + i * 8];
        Wh[(size_t)(h0 + ty + i * 8) * DD + d0 + tx] = __float2half_rn(v);
    }
}

// ---------------- kernel 3: fused GEMM (mma.sync) + relu + layer2 partials ----
// 512 threads, warp grid 4(m) x 4(n), 32x64 warp tiles, mbarrier free-run pipeline
// with lane-0-elected waits/arrives (empty count = 16 warps).
__device__ __forceinline__ void issue_chunk(uint32_t stg, const __half* A, const __half* B,
                                            int m0, int n0, int k0, int tid) {
#pragma unroll
    for (int i = 0; i < 2; i++) {               // A: 128 rows x 128B = 1024 x 16B
        int idx = i * 512 + tid, row = idx >> 3, kb = idx & 7;
        uint32_t off = (uint32_t)(row * 128 + kb * 16);
        CPA16(stg + (off ^ ((row & 7) << 4)), A + (size_t)(m0 + row) * DD + k0 + kb * 8);
    }
#pragma unroll
    for (int i = 0; i < 4; i++) {               // B: 256 rows x 128B = 2048 x 16B
        int idx = i * 512 + tid, row = idx >> 3, kb = idx & 7;
        uint32_t off = (uint32_t)(row * 128 + kb * 16);
        CPA16(stg + A_BYTES + (off ^ ((row & 7) << 4)), B + (size_t)(n0 + row) * DD + k0 + kb * 8);
    }
}

__global__ void __launch_bounds__(512, 1) gemm_kernel(
    const float* __restrict__ b1t, const float* __restrict__ w2t,
    const float* __restrict__ b1f, const float* __restrict__ w2f) {
    extern __shared__ char dsm[];
    uint32_t raw = smem_u32(dsm);
    uint32_t sb = (raw + 1023) & ~1023u;
    char* base = dsm + (sb - raw);
    float* b1s = (float*)(base);               // 256 f @0
    float* w2s = (float*)(base + 1024);        // 512 f @1024
    float* red = (float*)(base + 3072);        // 1024 f @3072..7168
    const uint32_t mb   = sb + 7168;           // 8 mbarriers: full[4], empty[4]
    const uint32_t stg0 = sb + 8192;

    int tid = threadIdx.x, wid = tid >> 5, lane = tid & 31;
    int wm = wid & 3, wn = wid >> 2;            // 4 x 4 warp grid, 32x64 tiles
    int e = blockIdx.y;
    int gid = blockIdx.x;
    int st = gid >> 6, w64 = gid & 63;          // 8x8 supertile
    int mtile = (st & 7) * 8 + (w64 & 7);
    int ntile = (st >> 3) * 8 + (w64 >> 3);
    int m0 = mtile * TM, n0 = ntile * TN;

    {
        const float* b1 = e ? b1f : b1t;
        const float* w2 = e ? w2f : w2t;
        if (tid < 256) {
            b1s[tid] = b1[n0 + tid];
            w2s[2 * tid]     = w2[(size_t)(n0 + tid) * 2];
            w2s[2 * tid + 1] = w2[(size_t)(n0 + tid) * 2 + 1];
        }
    }
    if (tid == 0) {
#pragma unroll
        for (int s = 0; s < 4; s++) {
            MBAR_INIT(mb + s * 8, 512);        // full[s]: 512 .noinc cp-arrives
            MBAR_INIT(mb + 32 + s * 8, 16);    // empty[s]: one arrive per warp (lane 0)
        }
    }
    __syncthreads();   // mbarriers + b1s/w2s visible

    const __half* X = reinterpret_cast<const __half*>(g_x4);
    const __half* W = reinterpret_cast<const __half*>(g_w4[e]);

    // ldmatrix per-lane addressing (swizzle mask constant across 8-row steps)
    uint32_t amask = (uint32_t)((lane & 7) << 4);
    uint32_t aoff0 = (uint32_t)((wm * 32 + ((lane >> 3) & 1) * 8 + (lane & 7)) * 128
                                + ((lane >> 4) & 1) * 16);
    uint32_t boff0 = (uint32_t)((wn * 64 + ((lane >> 4) & 1) * 8 + (lane & 7)) * 128
                                + ((lane >> 3) & 1) * 16);

    float acc[2][8][4];
#pragma unroll
    for (int i = 0; i < 2; i++)
#pragma unroll
        for (int j = 0; j < 8; j++)
#pragma unroll
            for (int q = 0; q < 4; q++) acc[i][j][q] = 0.f;

    // prologue: produce chunks 0..2 into stages 0..2
#pragma unroll
    for (int c = 0; c < 3; c++) {
        issue_chunk(stg0 + c * STAGE_BYTES, X, W, m0, n0, c * 64, tid);
        CPA_ARRIVE(mb + c * 8);
    }

    for (int kk = 0; kk < CHUNKS; kk++) {
        int s = kk & 3;
        MBAR_WAIT_W(mb + s * 8, (kk >> 2) & 1, lane);  // chunk kk landed (lane-0 poll)
        uint32_t sA = stg0 + s * STAGE_BYTES;
        uint32_t sB = sA + A_BYTES;
#pragma unroll
        for (int kt = 0; kt < 4; kt++) {
            uint32_t a[2][4], b[4][4];
#pragma unroll
            for (int i = 0; i < 2; i++)
                ldsm4(a[i], sA + ((aoff0 + i * 2048 + kt * 32) ^ amask));
#pragma unroll
            for (int j = 0; j < 4; j++)
                ldsm4(b[j], sB + ((boff0 + j * 2048 + kt * 32) ^ amask));
#pragma unroll
            for (int i = 0; i < 2; i++)
#pragma unroll
                for (int j8 = 0; j8 < 8; j8++)
                    mma16816(acc[i][j8], a[i], &b[j8 >> 1][(j8 & 1) * 2]);
        }
        // warp converged past mma.sync => all lanes' ldsm reads of stage s done
        if (lane == 0) MBAR_ARRIVE(mb + 32 + s * 8);

        int nk = kk + 3;
        if (nk < CHUNKS) {
            int ns = nk & 3;
            if (nk >= 4)                               // previous contents fully consumed?
                MBAR_WAIT_W(mb + 32 + ns * 8, ((nk >> 2) + 1) & 1, lane);
            issue_chunk(stg0 + ns * STAGE_BYTES, X, W, m0, n0, nk * 64, tid);
            CPA_ARRIVE(mb + ns * 8);
        }
    }
    __syncthreads();

    // epilogue: bias + relu + layer2 dot, per-thread partials
    float cc[2][2][2] = {{{0.f, 0.f}, {0.f, 0.f}}, {{0.f, 0.f}, {0.f, 0.f}}};
#pragma unroll
    for (int i = 0; i < 2; i++)
#pragma unroll
        for (int j8 = 0; j8 < 8; j8++) {
            int nc = wn * 64 + j8 * 8 + (lane & 3) * 2;
            float h;
            h = fmaxf(acc[i][j8][0] + b1s[nc], 0.f);
            cc[i][0][0] += h * w2s[2 * nc];     cc[i][0][1] += h * w2s[2 * nc + 1];
            h = fmaxf(acc[i][j8][1] + b1s[nc + 1], 0.f);
            cc[i][0][0] += h * w2s[2 * nc + 2]; cc[i][0][1] += h * w2s[2 * nc + 3];
            h = fmaxf(acc[i][j8][2] + b1s[nc], 0.f);
            cc[i][1][0] += h * w2s[2 * nc];     cc[i][1][1] += h * w2s[2 * nc + 1];
            h = fmaxf(acc[i][j8][3] + b1s[nc + 1], 0.f);
            cc[i][1][0] += h * w2s[2 * nc + 2]; cc[i][1][1] += h * w2s[2 * nc + 3];
        }
    // quad reduce (lanes sharing rows differ only in lane&3)
#pragma unroll
    for (int d = 1; d <= 2; d <<= 1)
#pragma unroll
        for (int i = 0; i < 2; i++)
#pragma unroll
            for (int rh = 0; rh < 2; rh++)
#pragma unroll
                for (int c = 0; c < 2; c++)
                    cc[i][rh][c] += __shfl_xor_sync(0xffffffffu, cc[i][rh][c], d);
    if ((lane & 3) == 0) {
#pragma unroll
        for (int i = 0; i < 2; i++)
#pragma unroll
            for (int rh = 0; rh < 2; rh++) {
                int r = wm * 32 + i * 16 + rh * 8 + (lane >> 2);
                red[(r * 4 + wn) * 2]     = cc[i][rh][0];
                red[(r * 4 + wn) * 2 + 1] = cc[i][rh][1];
            }
    }
    __syncthreads();
    if (tid < 256) {
        int r = tid >> 1, c = tid & 1;
        float s = red[(r * 4 + 0) * 2 + c] + red[(r * 4 + 1) * 2 + c]
                + red[(r * 4 + 2) * 2 + c] + red[(r * 4 + 3) * 2 + c];
        g_part[(((size_t)e * NT + ntile) * BB + (m0 + r)) * 2 + c] = s;
    }
}

// ---------------- kernel 4: reduce + select + flag near-threshold rows --------
__global__ void select_kernel(const float* __restrict__ b2t, const float* __restrict__ b2f,
                              float* __restrict__ out) {
    int r = blockIdx.x * 256 + threadIdx.x;
    float t0 = b2t[0], t1 = b2t[1], f0 = b2f[0], f1 = b2f[1];
    for (int nt = 0; nt < NT; nt++) {
        size_t ot = (((size_t)0 * NT + nt) * BB + r) * 2;
        size_t of = (((size_t)1 * NT + nt) * BB + r) * 2;
        t0 += g_part[ot];  t1 += g_part[ot + 1];
        f0 += g_part[of];  f1 += g_part[of + 1];
    }
    float ad = fabsf(t0 - t1);
    bool low = ad < LN4F;
    out[(size_t)r * 2]     = low ? f0 : t0;
    out[(size_t)r * 2 + 1] = low ? f1 : t1;
    if (fabsf(ad - LN4F) < GUARD) {
        int idx = atomicAdd(&g_nfix, 1);
        if (idx < MAXFIX) g_fixrows[idx] = r;
    }
}

// ---------------- kernel 5: exact fp32 recompute for flagged rows (R12 form) --
__global__ void fix1_kernel(const float* __restrict__ x,
                            const float* __restrict__ w1t, const float* __restrict__ b1t, const float* __restrict__ w2t,
                            const float* __restrict__ w1f, const float* __restrict__ b1f, const float* __restrict__ w2f) {
    int fy = blockIdx.y;
    if (fy >= g_nfix || fy >= MAXFIX) return;
    int e = blockIdx.z;
    int row = g_fixrows[fy];
    const float* w1 = e ? w1f : w1t;
    const float* b1 = e ? b1f : b1t;
    const float* w2 = e ? w2f : w2t;
    __shared__ float xs[DD];
    __shared__ float red[256][2];
    int tid = threadIdx.x;
    for (int i = tid; i < DD; i += 256) xs[i] = x[(size_t)row * DD + i];
    __syncthreads();
    int col = blockIdx.x * 256 + tid;
    float acc = 0.f;
    const float* wp = w1 + col;
#pragma unroll 4
    for (int d = 0; d < DD; d++) acc += xs[d] * wp[(size_t)d * HH];
    float h = fmaxf(acc + b1[col], 0.f);
    red[tid][0] = h * w2[(size_t)col * 2];
    red[tid][1] = h * w2[(size_t)col * 2 + 1];
    __syncthreads();
    for (int sdiv = 128; sdiv > 0; sdiv >>= 1) {
        if (tid < sdiv) { red[tid][0] += red[tid + sdiv][0]; red[tid][1] += red[tid + sdiv][1]; }
        __syncthreads();
    }
    if (tid == 0) {
        size_t o = (((size_t)e * MAXFIX + fy) * 32 + blockIdx.x) * 2;
        g_fixpart[o] = red[0][0];
        g_fixpart[o + 1] = red[0][1];
    }
}

__global__ void fix2_kernel(const float* __restrict__ b2t, const float* __restrict__ b2f,
                            float* __restrict__ out) {
    int fy = blockIdx.x;
    if (fy >= g_nfix || fy >= MAXFIX || threadIdx.x != 0) return;
    int row = g_fixrows[fy];
    float t0 = b2t[0], t1 = b2t[1], f0 = b2f[0], f1 = b2f[1];
    for (int b = 0; b < 32; b++) {
        size_t ot = (((size_t)0 * MAXFIX + fy) * 32 + b) * 2;
        size_t of = (((size_t)1 * MAXFIX + fy) * 32 + b) * 2;
        t0 += g_fixpart[ot];  t1 += g_fixpart[ot + 1];
        f0 += g_fixpart[of];  f1 += g_fixpart[of + 1];
    }
    bool low = fabsf(t0 - t1) < LN4F;
    out[(size_t)row * 2]     = low ? f0 : t0;
    out[(size_t)row * 2 + 1] = low ? f1 : t1;
}

// ---------------- launch ----------------
extern "C" void kernel_launch(void* const* d_in, const int* in_sizes, int n_in,
                              void* d_out, int out_size) {
    const float* x   = (const float*)d_in[0];
    const float* tw1 = (const float*)d_in[1];
    const float* tb1 = (const float*)d_in[2];
    const float* tw2 = (const float*)d_in[3];
    const float* tb2 = (const float*)d_in[4];
    const float* fw1 = (const float*)d_in[5];
    const float* fb1 = (const float*)d_in[6];
    const float* fw2 = (const float*)d_in[7];
    const float* fb2 = (const float*)d_in[8];
    float* out = (float*)d_out;
    (void)in_sizes; (void)n_in; (void)out_size;

    cvt_x_kernel<<<(BB * DD / 4 + 255) / 256, 256>>>(x);
    cvt_w_kernel<<<dim3(HH / 32, DD / 32, 2), dim3(32, 8)>>>(tw1, fw1);
    cudaFuncSetAttribute(gemm_kernel, cudaFuncAttributeMaxDynamicSharedMemorySize, SMEM_DYN);
    gemm_kernel<<<dim3(MT * NT, 2, 1), 512, SMEM_DYN>>>(tb1, tw2, fb1, fw2);
    select_kernel<<<BB / 256, 256>>>(tb2, fb2, out);
    fix1_kernel<<<dim3(HH / 256, MAXFIX, 2), 256>>>(x, tw1, tb1, tw2, fw1, fb1, fw2);
    fix2_kernel<<<MAXFIX, 32>>>(tb2, fb2, out);
}

// round 17
// speedup vs baseline: 1.5460x; 1.5460x over previous
#include <cuda_runtime.h>
#include <cuda_fp16.h>
#include <cstdint>
#include <cstddef>

#define BB 8192
#define DD 4096
#define HH 8192
#define TM 128
#define TN 256
#define CHUNKS 64             // 64 k-chunks of 64
#define NT 32
#define MT 64
#define A_BYTES 16384         // 128 rows * 128B
#define B_BYTES 32768         // 256 rows * 128B
#define STAGE_BYTES (A_BYTES + B_BYTES)
#define SMEM_DYN (1024 + 8192 + 4 * STAGE_BYTES)   // 205824
#define LN4F 1.3862944f
#define GUARD 2e-3f
#define MAXFIX 128

// ---------------- device scratch ----------------
__device__ uint4 g_x4[(size_t)BB * DD / 8];             // x as fp16
__device__ uint4 g_w4[2][(size_t)HH * DD / 8];          // [expert] w1^T fp16
__device__ float g_part[(size_t)2 * NT * BB * 2];
__device__ int   g_nfix;
__device__ int   g_fixrows[MAXFIX];
__device__ float g_fixpart[2 * MAXFIX * 32 * 2];

// ---------------- helpers ----------------
__device__ __forceinline__ uint32_t smem_u32(const void* p) {
    uint32_t a;
    asm("{ .reg .u64 t; cvta.to.shared.u64 t, %1; cvt.u32.u64 %0, t; }" : "=r"(a) : "l"(p));
    return a;
}
#define CPA16(sa, g) asm volatile("cp.async.cg.shared.global [%0], [%1], 16;" :: "r"(sa), "l"(g) : "memory")
// .noinc: arrive against the PRE-INITIALIZED expected count (the default form
// self-increments pending count -> net-zero -> permanent deadlock).
#define CPA_ARRIVE(a) asm volatile("cp.async.mbarrier.arrive.noinc.shared.b64 [%0];" :: "r"((uint32_t)(a)) : "memory")
#define MBAR_INIT(a, c) asm volatile("mbarrier.init.shared.b64 [%0], %1;" :: "r"((uint32_t)(a)), "r"((uint32_t)(c)) : "memory")
#define MBAR_ARRIVE(a) asm volatile("mbarrier.arrive.shared.b64 _, [%0];" :: "r"((uint32_t)(a)) : "memory")
#define MBAR_WAIT(a, ph) do { \
    uint32_t _m = (uint32_t)(a), _p = (uint32_t)(ph), _d; \
    asm volatile("{.reg .pred p; mbarrier.try_wait.parity.acquire.cta.shared::cta.b64 p, [%1], %2; selp.b32 %0,1,0,p;}" \
        : "=r"(_d) : "r"(_m), "r"(_p) : "memory"); \
    if (!_d) asm volatile("{.reg .pred P1; WL_%=: mbarrier.try_wait.parity.acquire.cta.shared::cta.b64 P1, [%0], %1, 0x989680; @P1 bra.uni WD_%=; bra.uni WL_%=; WD_%=:}" \
        :: "r"(_m), "r"(_p) : "memory"); \
} while (0)

__device__ __forceinline__ void ldsm4(uint32_t* r, uint32_t addr) {
    asm volatile("ldmatrix.sync.aligned.m8n8.x4.shared.b16 {%0,%1,%2,%3}, [%4];"
                 : "=r"(r[0]), "=r"(r[1]), "=r"(r[2]), "=r"(r[3]) : "r"(addr));
}
__device__ __forceinline__ void mma16816(float* d, const uint32_t* a, const uint32_t* b) {
    asm volatile("mma.sync.aligned.m16n8k16.row.col.f32.f16.f16.f32 "
                 "{%0,%1,%2,%3}, {%4,%5,%6,%7}, {%8,%9}, {%0,%1,%2,%3};"
                 : "+f"(d[0]), "+f"(d[1]), "+f"(d[2]), "+f"(d[3])
                 : "r"(a[0]), "r"(a[1]), "r"(a[2]), "r"(a[3]), "r"(b[0]), "r"(b[1]));
}

// ---------------- kernel 1: x -> fp16 ----------------
__global__ void cvt_x_kernel(const float* __restrict__ x) {
    if (blockIdx.x == 0 && threadIdx.x == 0) g_nfix = 0;
    size_t i = (size_t)blockIdx.x * blockDim.x + threadIdx.x;
    if (i >= (size_t)BB * DD / 4) return;
    float4 v = reinterpret_cast<const float4*>(x)[i];
    __half2* px = reinterpret_cast<__half2*>(g_x4);
    px[2 * i]     = __floats2half2_rn(v.x, v.y);
    px[2 * i + 1] = __floats2half2_rn(v.z, v.w);
}

// ---------------- kernel 2: w1 [D,H] f32 -> W [H,D] fp16 (transpose) ----------
__global__ void cvt_w_kernel(const float* __restrict__ wt, const float* __restrict__ wf) {
    __shared__ float tile[32][33];
    const float* w = blockIdx.z ? wf : wt;
    __half* Wh = reinterpret_cast<__half*>(g_w4[blockIdx.z]);
    int h0 = blockIdx.x * 32, d0 = blockIdx.y * 32;
    int tx = threadIdx.x, ty = threadIdx.y;   // (32, 8)
#pragma unroll
    for (int i = 0; i < 4; i++)
        tile[ty + i * 8][tx] = w[(size_t)(d0 + ty + i * 8) * HH + h0 + tx];
    __syncthreads();
#pragma unroll
    for (int i = 0; i < 4; i++) {
        float v = tile[tx][ty + i * 8];
        Wh[(size_t)(h0 + ty + i * 8) * DD + d0 + tx] = __float2half_rn(v);
    }
}

// ---------------- kernel 3: fused GEMM (mma.sync) + relu + layer2 partials ----
// 512 threads, warp grid 4(m) x 4(n), 32x64 warp tiles, mbarrier free-run pipeline.
__device__ __forceinline__ void issue_chunk(uint32_t stg, const __half* A, const __half* B,
                                            int m0, int n0, int k0, int tid) {
#pragma unroll
    for (int i = 0; i < 2; i++) {               // A: 128 rows x 128B = 1024 x 16B
        int idx = i * 512 + tid, row = idx >> 3, kb = idx & 7;
        uint32_t off = (uint32_t)(row * 128 + kb * 16);
        CPA16(stg + (off ^ ((row & 7) << 4)), A + (size_t)(m0 + row) * DD + k0 + kb * 8);
    }
#pragma unroll
    for (int i = 0; i < 4; i++) {               // B: 256 rows x 128B = 2048 x 16B
        int idx = i * 512 + tid, row = idx >> 3, kb = idx & 7;
        uint32_t off = (uint32_t)(row * 128 + kb * 16);
        CPA16(stg + A_BYTES + (off ^ ((row & 7) << 4)), B + (size_t)(n0 + row) * DD + k0 + kb * 8);
    }
}

__global__ void __launch_bounds__(512, 1) gemm_kernel(
    const float* __restrict__ b1t, const float* __restrict__ w2t,
    const float* __restrict__ b1f, const float* __restrict__ w2f) {
    extern __shared__ char dsm[];
    uint32_t raw = smem_u32(dsm);
    uint32_t sb = (raw + 1023) & ~1023u;
    char* base = dsm + (sb - raw);
    float* b1s = (float*)(base);               // 256 f @0
    float* w2s = (float*)(base + 1024);        // 512 f @1024
    float* red = (float*)(base + 3072);        // 1024 f @3072..7168
    const uint32_t mb   = sb + 7168;           // 8 mbarriers: full[4], empty[4]
    const uint32_t stg0 = sb + 8192;

    int tid = threadIdx.x, wid = tid >> 5, lane = tid & 31;
    int wm = wid & 3, wn = wid >> 2;            // 4 x 4 warp grid, 32x64 tiles
    int e = blockIdx.y;
    int gid = blockIdx.x;
    int st = gid >> 6, w64 = gid & 63;          // 8x8 supertile
    int mtile = (st & 7) * 8 + (w64 & 7);
    int ntile = (st >> 3) * 8 + (w64 >> 3);
    int m0 = mtile * TM, n0 = ntile * TN;

    {
        const float* b1 = e ? b1f : b1t;
        const float* w2 = e ? w2f : w2t;
        if (tid < 256) {
            b1s[tid] = b1[n0 + tid];
            w2s[2 * tid]     = w2[(size_t)(n0 + tid) * 2];
            w2s[2 * tid + 1] = w2[(size_t)(n0 + tid) * 2 + 1];
        }
    }
    if (tid == 0) {
#pragma unroll
        for (int s = 0; s < 4; s++) {
            MBAR_INIT(mb + s * 8, 512);        // full[s]: 512 .noinc cp-arrives
            MBAR_INIT(mb + 32 + s * 8, 512);   // empty[s]: 512 plain arrives
        }
    }
    __syncthreads();   // mbarriers + b1s/w2s visible

    const __half* X = reinterpret_cast<const __half*>(g_x4);
    const __half* W = reinterpret_cast<const __half*>(g_w4[e]);

    // ldmatrix per-lane addressing (swizzle mask constant across 8-row steps)
    uint32_t amask = (uint32_t)((lane & 7) << 4);
    uint32_t aoff0 = (uint32_t)((wm * 32 + ((lane >> 3) & 1) * 8 + (lane & 7)) * 128
                                + ((lane >> 4) & 1) * 16);
    uint32_t boff0 = (uint32_t)((wn * 64 + ((lane >> 4) & 1) * 8 + (lane & 7)) * 128
                                + ((lane >> 3) & 1) * 16);

    float acc[2][8][4];
#pragma unroll
    for (int i = 0; i < 2; i++)
#pragma unroll
        for (int j = 0; j < 8; j++)
#pragma unroll
            for (int q = 0; q < 4; q++) acc[i][j][q] = 0.f;

    // prologue: produce chunks 0..2 into stages 0..2
#pragma unroll
    for (int c = 0; c < 3; c++) {
        issue_chunk(stg0 + c * STAGE_BYTES, X, W, m0, n0, c * 64, tid);
        CPA_ARRIVE(mb + c * 8);
    }

    for (int kk = 0; kk < CHUNKS; kk++) {
        int s = kk & 3;
        MBAR_WAIT(mb + s * 8, (kk >> 2) & 1);          // chunk kk data landed (all threads)
        uint32_t sA = stg0 + s * STAGE_BYTES;
        uint32_t sB = sA + A_BYTES;
#pragma unroll
        for (int kt = 0; kt < 4; kt++) {
            uint32_t a[2][4], b[4][4];
#pragma unroll
            for (int i = 0; i < 2; i++)
                ldsm4(a[i], sA + ((aoff0 + i * 2048 + kt * 32) ^ amask));
#pragma unroll
            for (int j = 0; j < 4; j++)
                ldsm4(b[j], sB + ((boff0 + j * 2048 + kt * 32) ^ amask));
#pragma unroll
            for (int i = 0; i < 2; i++)
#pragma unroll
                for (int j8 = 0; j8 < 8; j8++)
                    mma16816(acc[i][j8], a[i], &b[j8 >> 1][(j8 & 1) * 2]);
        }
        MBAR_ARRIVE(mb + 32 + s * 8);                  // this thread done reading stage s

        int nk = kk + 3;
        if (nk < CHUNKS) {
            int ns = nk & 3;
            if (nk >= 4)                               // previous contents fully consumed?
                MBAR_WAIT(mb + 32 + ns * 8, ((nk >> 2) + 1) & 1);
            issue_chunk(stg0 + ns * STAGE_BYTES, X, W, m0, n0, nk * 64, tid);
            CPA_ARRIVE(mb + ns * 8);
        }
    }
    __syncthreads();

    // epilogue: bias + relu + layer2 dot, per-thread partials
    float cc[2][2][2] = {{{0.f, 0.f}, {0.f, 0.f}}, {{0.f, 0.f}, {0.f, 0.f}}};
#pragma unroll
    for (int i = 0; i < 2; i++)
#pragma unroll
        for (int j8 = 0; j8 < 8; j8++) {
            int nc = wn * 64 + j8 * 8 + (lane & 3) * 2;
            float h;
            h = fmaxf(acc[i][j8][0] + b1s[nc], 0.f);
            cc[i][0][0] += h * w2s[2 * nc];     cc[i][0][1] += h * w2s[2 * nc + 1];
            h = fmaxf(acc[i][j8][1] + b1s[nc + 1], 0.f);
            cc[i][0][0] += h * w2s[2 * nc + 2]; cc[i][0][1] += h * w2s[2 * nc + 3];
            h = fmaxf(acc[i][j8][2] + b1s[nc], 0.f);
            cc[i][1][0] += h * w2s[2 * nc];     cc[i][1][1] += h * w2s[2 * nc + 1];
            h = fmaxf(acc[i][j8][3] + b1s[nc + 1], 0.f);
            cc[i][1][0] += h * w2s[2 * nc + 2]; cc[i][1][1] += h * w2s[2 * nc + 3];
        }
    // quad reduce (lanes sharing rows differ only in lane&3)
#pragma unroll
    for (int d = 1; d <= 2; d <<= 1)
#pragma unroll
        for (int i = 0; i < 2; i++)
#pragma unroll
            for (int rh = 0; rh < 2; rh++)
#pragma unroll
                for (int c = 0; c < 2; c++)
                    cc[i][rh][c] += __shfl_xor_sync(0xffffffffu, cc[i][rh][c], d);
    if ((lane & 3) == 0) {
#pragma unroll
        for (int i = 0; i < 2; i++)
#pragma unroll
            for (int rh = 0; rh < 2; rh++) {
                int r = wm * 32 + i * 16 + rh * 8 + (lane >> 2);
                red[(r * 4 + wn) * 2]     = cc[i][rh][0];
                red[(r * 4 + wn) * 2 + 1] = cc[i][rh][1];
            }
    }
    __syncthreads();
    if (tid < 256) {
        int r = tid >> 1, c = tid & 1;
        float s = red[(r * 4 + 0) * 2 + c] + red[(r * 4 + 1) * 2 + c]
                + red[(r * 4 + 2) * 2 + c] + red[(r * 4 + 3) * 2 + c];
        g_part[(((size_t)e * NT + ntile) * BB + (m0 + r)) * 2 + c] = s;
    }
}

// ---------------- kernel 4: reduce + select + flag near-threshold rows --------
__global__ void select_kernel(const float* __restrict__ b2t, const float* __restrict__ b2f,
                              float* __restrict__ out) {
    int r = blockIdx.x * 256 + threadIdx.x;
    float t0 = b2t[0], t1 = b2t[1], f0 = b2f[0], f1 = b2f[1];
    for (int nt = 0; nt < NT; nt++) {
        size_t ot = (((size_t)0 * NT + nt) * BB + r) * 2;
        size_t of = (((size_t)1 * NT + nt) * BB + r) * 2;
        t0 += g_part[ot];  t1 += g_part[ot + 1];
        f0 += g_part[of];  f1 += g_part[of + 1];
    }
    float ad = fabsf(t0 - t1);
    bool low = ad < LN4F;
    out[(size_t)r * 2]     = low ? f0 : t0;
    out[(size_t)r * 2 + 1] = low ? f1 : t1;
    if (fabsf(ad - LN4F) < GUARD) {
        int idx = atomicAdd(&g_nfix, 1);
        if (idx < MAXFIX) g_fixrows[idx] = r;
    }
}

// ---------------- kernel 5: exact fp32 recompute for flagged rows -------------
__global__ void fix1_kernel(const float* __restrict__ x,
                            const float* __restrict__ w1t, const float* __restrict__ b1t, const float* __restrict__ w2t,
                            const float* __restrict__ w1f, const float* __restrict__ b1f, const float* __restrict__ w2f) {
    int fy = blockIdx.y;
    if (fy >= g_nfix || fy >= MAXFIX) return;
    int e = blockIdx.z;
    int row = g_fixrows[fy];
    const float* w1 = e ? w1f : w1t;
    const float* b1 = e ? b1f : b1t;
    const float* w2 = e ? w2f : w2t;
    __shared__ float xs[DD];
    __shared__ float red[256][2];
    int tid = threadIdx.x;
    for (int i = tid; i < DD; i += 256) xs[i] = x[(size_t)row * DD + i];
    __syncthreads();
    int col = blockIdx.x * 256 + tid;
    float acc = 0.f;
    const float* wp = w1 + col;
#pragma unroll 4
    for (int d = 0; d < DD; d++) acc += xs[d] * wp[(size_t)d * HH];
    float h = fmaxf(acc + b1[col], 0.f);
    red[tid][0] = h * w2[(size_t)col * 2];
    red[tid][1] = h * w2[(size_t)col * 2 + 1];
    __syncthreads();
    for (int sdiv = 128; sdiv > 0; sdiv >>= 1) {
        if (tid < sdiv) { red[tid][0] += red[tid + sdiv][0]; red[tid][1] += red[tid + sdiv][1]; }
        __syncthreads();
    }
    if (tid == 0) {
        size_t o = (((size_t)e * MAXFIX + fy) * 32 + blockIdx.x) * 2;
        g_fixpart[o] = red[0][0];
        g_fixpart[o + 1] = red[0][1];
    }
}

__global__ void fix2_kernel(const float* __restrict__ b2t, const float* __restrict__ b2f,
                            float* __restrict__ out) {
    int fy = blockIdx.x;
    if (fy >= g_nfix || fy >= MAXFIX || threadIdx.x != 0) return;
    int row = g_fixrows[fy];
    float t0 = b2t[0], t1 = b2t[1], f0 = b2f[0], f1 = b2f[1];
    for (int b = 0; b < 32; b++) {
        size_t ot = (((size_t)0 * MAXFIX + fy) * 32 + b) * 2;
        size_t of = (((size_t)1 * MAXFIX + fy) * 32 + b) * 2;
        t0 += g_fixpart[ot];  t1 += g_fixpart[ot + 1];
        f0 += g_fixpart[of];  f1 += g_fixpart[of + 1];
    }
    bool low = fabsf(t0 - t1) < LN4F;
    out[(size_t)row * 2]     = low ? f0 : t0;
    out[(size_t)row * 2 + 1] = low ? f1 : t1;
}

// ---------------- launch ----------------
extern "C" void kernel_launch(void* const* d_in, const int* in_sizes, int n_in,
                              void* d_out, int out_size) {
    const float* x   = (const float*)d_in[0];
    const float* tw1 = (const float*)d_in[1];
    const float* tb1 = (const float*)d_in[2];
    const float* tw2 = (const float*)d_in[3];
    const float* tb2 = (const float*)d_in[4];
    const float* fw1 = (const float*)d_in[5];
    const float* fb1 = (const float*)d_in[6];
    const float* fw2 = (const float*)d_in[7];
    const float* fb2 = (const float*)d_in[8];
    float* out = (float*)d_out;
    (void)in_sizes; (void)n_in; (void)out_size;

    cvt_x_kernel<<<(BB * DD / 4 + 255) / 256, 256>>>(x);
    cvt_w_kernel<<<dim3(HH / 32, DD / 32, 2), dim3(32, 8)>>>(tw1, fw1);
    cudaFuncSetAttribute(gemm_kernel, cudaFuncAttributeMaxDynamicSharedMemorySize, SMEM_DYN);
    gemm_kernel<<<dim3(MT * NT, 2, 1), 512, SMEM_DYN>>>(tb1, tw2, fb1, fw2);
    select_kernel<<<BB / 256, 256>>>(tb2, fb2, out);
    fix1_kernel<<<dim3(HH / 256, MAXFIX, 2), 256>>>(x, tw1, tb1, tw2, fw1, fb1, fw2);
    fix2_kernel<<<MAXFIX, 32>>>(tb2, fb2, out);
}